// round 1
// baseline (speedup 1.0000x reference)
#include <cuda_runtime.h>
#include <cuda_bf16.h>

#define BATCH 8
#define NDIM  16384
#define CDIM  512

// Scratch: energy[b][i][j] and the folded matrix M[b][j][i] = gamma*att[i][j] + I
__device__ float g_energy[BATCH * CDIM * CDIM];
__device__ float g_M[BATCH * CDIM * CDIM];

#define TILE 64
#define KT   32

// ---------------------------------------------------------------------------
// Kernel 1: per-batch Gram matrix  E = X^T X  (X = x[b] as [N, C], C contig).
// E[i][j] = sum_n X[n][i] * X[n][j].  Symmetric: compute jt >= it, mirror.
// Grid (8, 8, BATCH), 256 threads, 4x4 register tile per thread.
// ---------------------------------------------------------------------------
__global__ void gram_kernel(const float* __restrict__ x) {
    int it = blockIdx.x, jt = blockIdx.y, b = blockIdx.z;
    if (jt < it) return;

    __shared__ float As[KT][TILE + 4];
    __shared__ float Bs[KT][TILE + 4];

    int t  = threadIdx.x;
    int ty = t >> 4;          // 0..15 -> i sub-tile
    int tx = t & 15;          // 0..15 -> j sub-tile

    const float* Xb = x + (size_t)b * NDIM * CDIM;
    int i0 = it * TILE, j0 = jt * TILE;

    float acc[4][4] = {};

    for (int n0 = 0; n0 < NDIM; n0 += KT) {
        #pragma unroll
        for (int e = 0; e < (KT * TILE) / 256; e++) {
            int idx = t + e * 256;
            int kk = idx >> 6;       // /64
            int cc = idx & 63;
            size_t row = (size_t)(n0 + kk) * CDIM;
            As[kk][cc] = Xb[row + i0 + cc];
            Bs[kk][cc] = Xb[row + j0 + cc];
        }
        __syncthreads();

        #pragma unroll
        for (int kk = 0; kk < KT; kk++) {
            float a[4], bb[4];
            #pragma unroll
            for (int r = 0; r < 4; r++) a[r]  = As[kk][ty * 4 + r];
            #pragma unroll
            for (int r = 0; r < 4; r++) bb[r] = Bs[kk][tx * 4 + r];
            #pragma unroll
            for (int ri = 0; ri < 4; ri++)
                #pragma unroll
                for (int rj = 0; rj < 4; rj++)
                    acc[ri][rj] += a[ri] * bb[rj];
        }
        __syncthreads();
    }

    float* Eb = g_energy + (size_t)b * CDIM * CDIM;
    #pragma unroll
    for (int ri = 0; ri < 4; ri++) {
        #pragma unroll
        for (int rj = 0; rj < 4; rj++) {
            int gi = i0 + ty * 4 + ri;
            int gj = j0 + tx * 4 + rj;
            Eb[(size_t)gi * CDIM + gj] = acc[ri][rj];
            if (it != jt) Eb[(size_t)gj * CDIM + gi] = acc[ri][rj];
        }
    }
}

// ---------------------------------------------------------------------------
// Kernel 2: softmax(rowmax - E) over j == softmax(-E) == exp(min_i - E)/sum.
// Builds M[j][i] = gamma * att[i][j] + (i==j).
// Grid (CDIM, BATCH), 256 threads; each thread owns 2 j's of row i.
// ---------------------------------------------------------------------------
__global__ void softmax_build_M_kernel(const float* __restrict__ gamma_p) {
    int i = blockIdx.x, b = blockIdx.y;
    const float* e = g_energy + ((size_t)b * CDIM + i) * CDIM;

    __shared__ float sm[256];
    int t = threadIdx.x;

    float v0 = e[t];
    float v1 = e[t + 256];

    // block-reduce min
    sm[t] = fminf(v0, v1);
    __syncthreads();
    for (int s = 128; s > 0; s >>= 1) {
        if (t < s) sm[t] = fminf(sm[t], sm[t + s]);
        __syncthreads();
    }
    float mn = sm[0];
    __syncthreads();

    float w0 = __expf(mn - v0);
    float w1 = __expf(mn - v1);

    // block-reduce sum
    sm[t] = w0 + w1;
    __syncthreads();
    for (int s = 128; s > 0; s >>= 1) {
        if (t < s) sm[t] += sm[t + s];
        __syncthreads();
    }
    float inv = gamma_p[0] / sm[0];

    float* Mb = g_M + (size_t)b * CDIM * CDIM;
    int j0 = t, j1 = t + 256;
    Mb[(size_t)j0 * CDIM + i] = w0 * inv + (j0 == i ? 1.0f : 0.0f);
    Mb[(size_t)j1 * CDIM + i] = w1 * inv + (j1 == i ? 1.0f : 0.0f);
}

// ---------------------------------------------------------------------------
// Kernel 3: Y = X @ M   (gamma and the +v residual are folded into M).
// X: [N, C] row-major, M: [C, C] row-major ([j][i]), Y: [N, C] ([n][i]).
// Grid (N/TILE, C/TILE, BATCH), 256 threads, 4x4 register tile.
// ---------------------------------------------------------------------------
__global__ void out_gemm_kernel(const float* __restrict__ x,
                                float* __restrict__ y) {
    int nt = blockIdx.x, itile = blockIdx.y, b = blockIdx.z;

    __shared__ float As[TILE][KT + 1];   // X[n][k]
    __shared__ float Bs[KT][TILE + 4];   // M[k][i]

    int t  = threadIdx.x;
    int ty = t >> 4;
    int tx = t & 15;

    const float* Xb = x   + (size_t)b * NDIM * CDIM;
    const float* Mb = g_M + (size_t)b * CDIM * CDIM;
    int n0 = nt * TILE, i0 = itile * TILE;

    float acc[4][4] = {};

    for (int k0 = 0; k0 < CDIM; k0 += KT) {
        #pragma unroll
        for (int e = 0; e < (TILE * KT) / 256; e++) {
            int idx = t + e * 256;
            int nn = idx >> 5;       // /32
            int kk = idx & 31;
            As[nn][kk] = Xb[(size_t)(n0 + nn) * CDIM + k0 + kk];
        }
        #pragma unroll
        for (int e = 0; e < (KT * TILE) / 256; e++) {
            int idx = t + e * 256;
            int kk = idx >> 6;
            int ii = idx & 63;
            Bs[kk][ii] = Mb[(size_t)(k0 + kk) * CDIM + i0 + ii];
        }
        __syncthreads();

        #pragma unroll
        for (int kk = 0; kk < KT; kk++) {
            float a[4], bb[4];
            #pragma unroll
            for (int r = 0; r < 4; r++) a[r]  = As[ty * 4 + r][kk];
            #pragma unroll
            for (int r = 0; r < 4; r++) bb[r] = Bs[kk][tx * 4 + r];
            #pragma unroll
            for (int ri = 0; ri < 4; ri++)
                #pragma unroll
                for (int rj = 0; rj < 4; rj++)
                    acc[ri][rj] += a[ri] * bb[rj];
        }
        __syncthreads();
    }

    float* Yb = y + (size_t)b * NDIM * CDIM;
    #pragma unroll
    for (int ri = 0; ri < 4; ri++) {
        #pragma unroll
        for (int rj = 0; rj < 4; rj++) {
            Yb[(size_t)(n0 + ty * 4 + ri) * CDIM + i0 + tx * 4 + rj] =
                acc[ri][rj];
        }
    }
}

// ---------------------------------------------------------------------------
extern "C" void kernel_launch(void* const* d_in, const int* in_sizes, int n_in,
                              void* d_out, int out_size) {
    const float* x     = (const float*)d_in[0];
    const float* gamma = (const float*)d_in[1];
    float*       y     = (float*)d_out;

    (void)in_sizes; (void)n_in; (void)out_size;

    dim3 g1(CDIM / TILE, CDIM / TILE, BATCH);   // (8, 8, 8)
    gram_kernel<<<g1, 256>>>(x);

    dim3 g2(CDIM, BATCH);                       // (512, 8)
    softmax_build_M_kernel<<<g2, 256>>>(gamma);

    dim3 g3(NDIM / TILE, CDIM / TILE, BATCH);   // (256, 8, 8)
    out_gemm_kernel<<<g3, 256>>>(x, y);
}

// round 2
// speedup vs baseline: 1.0007x; 1.0007x over previous
#include <cuda_runtime.h>
#include <cuda_bf16.h>

#define BATCH 8
#define NDIM  16384
#define CDIM  512

// Scratch: energy[b][i][j] and the folded matrix M[b][j][i] = gamma*att[i][j] + I
__device__ float g_energy[BATCH * CDIM * CDIM];
__device__ float g_M[BATCH * CDIM * CDIM];

#define TILE 64
#define KT   32

// ---------------------------------------------------------------------------
// Kernel 1: per-batch Gram matrix  E = X^T X  (X = x[b] as [N, C], C contig).
// E[i][j] = sum_n X[n][i] * X[n][j].  Symmetric: compute jt >= it, mirror.
// Grid (8, 8, BATCH), 256 threads, 4x4 register tile per thread.
// ---------------------------------------------------------------------------
__global__ void gram_kernel(const float* __restrict__ x) {
    int it = blockIdx.x, jt = blockIdx.y, b = blockIdx.z;
    if (jt < it) return;

    __shared__ float As[KT][TILE + 4];
    __shared__ float Bs[KT][TILE + 4];

    int t  = threadIdx.x;
    int ty = t >> 4;          // 0..15 -> i sub-tile
    int tx = t & 15;          // 0..15 -> j sub-tile

    const float* Xb = x + (size_t)b * NDIM * CDIM;
    int i0 = it * TILE, j0 = jt * TILE;

    float acc[4][4] = {};

    for (int n0 = 0; n0 < NDIM; n0 += KT) {
        #pragma unroll
        for (int e = 0; e < (KT * TILE) / 256; e++) {
            int idx = t + e * 256;
            int kk = idx >> 6;       // /64
            int cc = idx & 63;
            size_t row = (size_t)(n0 + kk) * CDIM;
            As[kk][cc] = Xb[row + i0 + cc];
            Bs[kk][cc] = Xb[row + j0 + cc];
        }
        __syncthreads();

        #pragma unroll
        for (int kk = 0; kk < KT; kk++) {
            float a[4], bb[4];
            #pragma unroll
            for (int r = 0; r < 4; r++) a[r]  = As[kk][ty * 4 + r];
            #pragma unroll
            for (int r = 0; r < 4; r++) bb[r] = Bs[kk][tx * 4 + r];
            #pragma unroll
            for (int ri = 0; ri < 4; ri++)
                #pragma unroll
                for (int rj = 0; rj < 4; rj++)
                    acc[ri][rj] += a[ri] * bb[rj];
        }
        __syncthreads();
    }

    float* Eb = g_energy + (size_t)b * CDIM * CDIM;
    #pragma unroll
    for (int ri = 0; ri < 4; ri++) {
        #pragma unroll
        for (int rj = 0; rj < 4; rj++) {
            int gi = i0 + ty * 4 + ri;
            int gj = j0 + tx * 4 + rj;
            Eb[(size_t)gi * CDIM + gj] = acc[ri][rj];
            if (it != jt) Eb[(size_t)gj * CDIM + gi] = acc[ri][rj];
        }
    }
}

// ---------------------------------------------------------------------------
// Kernel 2: softmax(rowmax - E) over j == softmax(-E) == exp(min_i - E)/sum.
// Builds M[j][i] = gamma * att[i][j] + (i==j).
// Grid (CDIM, BATCH), 256 threads; each thread owns 2 j's of row i.
// ---------------------------------------------------------------------------
__global__ void softmax_build_M_kernel(const float* __restrict__ gamma_p) {
    int i = blockIdx.x, b = blockIdx.y;
    const float* e = g_energy + ((size_t)b * CDIM + i) * CDIM;

    __shared__ float sm[256];
    int t = threadIdx.x;

    float v0 = e[t];
    float v1 = e[t + 256];

    // block-reduce min
    sm[t] = fminf(v0, v1);
    __syncthreads();
    for (int s = 128; s > 0; s >>= 1) {
        if (t < s) sm[t] = fminf(sm[t], sm[t + s]);
        __syncthreads();
    }
    float mn = sm[0];
    __syncthreads();

    float w0 = __expf(mn - v0);
    float w1 = __expf(mn - v1);

    // block-reduce sum
    sm[t] = w0 + w1;
    __syncthreads();
    for (int s = 128; s > 0; s >>= 1) {
        if (t < s) sm[t] += sm[t + s];
        __syncthreads();
    }
    float inv = gamma_p[0] / sm[0];

    float* Mb = g_M + (size_t)b * CDIM * CDIM;
    int j0 = t, j1 = t + 256;
    Mb[(size_t)j0 * CDIM + i] = w0 * inv + (j0 == i ? 1.0f : 0.0f);
    Mb[(size_t)j1 * CDIM + i] = w1 * inv + (j1 == i ? 1.0f : 0.0f);
}

// ---------------------------------------------------------------------------
// Kernel 3: Y = X @ M   (gamma and the +v residual are folded into M).
// X: [N, C] row-major, M: [C, C] row-major ([j][i]), Y: [N, C] ([n][i]).
// Grid (N/TILE, C/TILE, BATCH), 256 threads, 4x4 register tile.
// ---------------------------------------------------------------------------
__global__ void out_gemm_kernel(const float* __restrict__ x,
                                float* __restrict__ y) {
    int nt = blockIdx.x, itile = blockIdx.y, b = blockIdx.z;

    __shared__ float As[TILE][KT + 1];   // X[n][k]
    __shared__ float Bs[KT][TILE + 4];   // M[k][i]

    int t  = threadIdx.x;
    int ty = t >> 4;
    int tx = t & 15;

    const float* Xb = x   + (size_t)b * NDIM * CDIM;
    const float* Mb = g_M + (size_t)b * CDIM * CDIM;
    int n0 = nt * TILE, i0 = itile * TILE;

    float acc[4][4] = {};

    for (int k0 = 0; k0 < CDIM; k0 += KT) {
        #pragma unroll
        for (int e = 0; e < (TILE * KT) / 256; e++) {
            int idx = t + e * 256;
            int nn = idx >> 5;       // /32
            int kk = idx & 31;
            As[nn][kk] = Xb[(size_t)(n0 + nn) * CDIM + k0 + kk];
        }
        #pragma unroll
        for (int e = 0; e < (KT * TILE) / 256; e++) {
            int idx = t + e * 256;
            int kk = idx >> 6;
            int ii = idx & 63;
            Bs[kk][ii] = Mb[(size_t)(k0 + kk) * CDIM + i0 + ii];
        }
        __syncthreads();

        #pragma unroll
        for (int kk = 0; kk < KT; kk++) {
            float a[4], bb[4];
            #pragma unroll
            for (int r = 0; r < 4; r++) a[r]  = As[ty * 4 + r][kk];
            #pragma unroll
            for (int r = 0; r < 4; r++) bb[r] = Bs[kk][tx * 4 + r];
            #pragma unroll
            for (int ri = 0; ri < 4; ri++)
                #pragma unroll
                for (int rj = 0; rj < 4; rj++)
                    acc[ri][rj] += a[ri] * bb[rj];
        }
        __syncthreads();
    }

    float* Yb = y + (size_t)b * NDIM * CDIM;
    #pragma unroll
    for (int ri = 0; ri < 4; ri++) {
        #pragma unroll
        for (int rj = 0; rj < 4; rj++) {
            Yb[(size_t)(n0 + ty * 4 + ri) * CDIM + i0 + tx * 4 + rj] =
                acc[ri][rj];
        }
    }
}

// ---------------------------------------------------------------------------
extern "C" void kernel_launch(void* const* d_in, const int* in_sizes, int n_in,
                              void* d_out, int out_size) {
    const float* x     = (const float*)d_in[0];
    const float* gamma = (const float*)d_in[1];
    float*       y     = (float*)d_out;

    (void)in_sizes; (void)n_in; (void)out_size;

    dim3 g1(CDIM / TILE, CDIM / TILE, BATCH);   // (8, 8, 8)
    gram_kernel<<<g1, 256>>>(x);

    dim3 g2(CDIM, BATCH);                       // (512, 8)
    softmax_build_M_kernel<<<g2, 256>>>(gamma);

    dim3 g3(NDIM / TILE, CDIM / TILE, BATCH);   // (256, 8, 8)
    out_gemm_kernel<<<g3, 256>>>(x, y);
}

// round 4
// speedup vs baseline: 2.0517x; 2.0503x over previous
#include <cuda_runtime.h>
#include <cuda_fp16.h>
#include <cstdint>

#define BATCH 8
#define NDIM  16384
#define CDIM  512

__device__ float g_Xt[(size_t)BATCH * CDIM * NDIM];     // [b][c][n]
__device__ float g_energy[(size_t)BATCH * CDIM * CDIM]; // [b][i][j]
__device__ float g_M[(size_t)BATCH * CDIM * CDIM];      // [b][i][k] = gamma*att + I

// ---- helpers -------------------------------------------------------------
__device__ __forceinline__ uint32_t s2u(const void* p) {
    uint32_t a;
    asm("{ .reg .u64 t; cvta.to.shared.u64 t, %1; cvt.u32.u64 %0, t; }" : "=r"(a) : "l"(p));
    return a;
}
__device__ __forceinline__ void ldm4(uint32_t* r, uint32_t a) {
    asm volatile("ldmatrix.sync.aligned.m8n8.x4.shared.b16 {%0,%1,%2,%3},[%4];"
                 : "=r"(r[0]), "=r"(r[1]), "=r"(r[2]), "=r"(r[3]) : "r"(a));
}
__device__ __forceinline__ void ldm2(uint32_t* r, uint32_t a) {
    asm volatile("ldmatrix.sync.aligned.m8n8.x2.shared.b16 {%0,%1},[%2];"
                 : "=r"(r[0]), "=r"(r[1]) : "r"(a));
}
__device__ __forceinline__ void mma16816(float* d, const uint32_t* a, const uint32_t* b) {
    asm volatile("mma.sync.aligned.m16n8k16.row.col.f32.f16.f16.f32 "
                 "{%0,%1,%2,%3},{%4,%5,%6,%7},{%8,%9},{%0,%1,%2,%3};"
                 : "+f"(d[0]), "+f"(d[1]), "+f"(d[2]), "+f"(d[3])
                 : "r"(a[0]), "r"(a[1]), "r"(a[2]), "r"(a[3]), "r"(b[0]), "r"(b[1]));
}

// smem layout: 2 buffers x 4 regions (AH, AL, BH, BL), each 128 rows x 24 halves
#define ROWH   24            // halves per row (16 data + 8 pad) -> 48B stride
#define REGB   (128 * ROWH * 2)   // 6144 bytes per region
#define RAH 0
#define RAL REGB
#define RBH (2 * REGB)
#define RBL (3 * REGB)
#define BUFB (4 * REGB)      // 24576 bytes per buffer
#define SMEM_TOT (2 * BUFB)  // 49152

// split-fp16 store: hi and lo of a float4 at half-offset `off` in each region
__device__ __forceinline__ void st_hl(char* hi, char* lo, uint32_t boff, float4 v) {
    __half hx = __float2half_rn(v.x), hy = __float2half_rn(v.y);
    __half hz = __float2half_rn(v.z), hw = __float2half_rn(v.w);
    __half lx = __float2half_rn(v.x - __half2float(hx));
    __half ly = __float2half_rn(v.y - __half2float(hy));
    __half lz = __float2half_rn(v.z - __half2float(hz));
    __half lw = __float2half_rn(v.w - __half2float(hw));
    *(__half2*)(hi + boff)     = __halves2half2(hx, hy);
    *(__half2*)(hi + boff + 4) = __halves2half2(hz, hw);
    *(__half2*)(lo + boff)     = __halves2half2(lx, ly);
    *(__half2*)(lo + boff + 4) = __halves2half2(lz, lw);
}

// ---------------------------------------------------------------------------
// Shared MMA pipeline: C(128x128) += A(128 x K) * B(128 x K)^T, K-major rows.
// A rows from pA (float, stride sA), B rows from pB (stride sB).
// 3-pass split-fp16. Result fp32 -> out (row stride so).
// ---------------------------------------------------------------------------
__device__ __forceinline__ void mma_pipe(const float* __restrict__ pA, size_t sA,
                                         const float* __restrict__ pB, size_t sB,
                                         int nst, float* __restrict__ out, size_t so) {
    extern __shared__ char smem[];
    const int tid  = threadIdx.x;
    const int lane = tid & 31;
    const int wm   = (tid >> 5) & 3;     // 4 warps along M
    const int wn   = tid >> 7;           // 2 warp groups along N
    const int mo   = wm * 32, no = wn * 64;
    const uint32_t sbase = s2u(smem);

    // per-lane ldmatrix sub-offsets (bytes)
    const uint32_t a_off = (uint32_t)(lane & 15) * 48 + (uint32_t)(lane >> 4) * 16;
    const uint32_t b_off = (uint32_t)(lane & 7)  * 48 + (uint32_t)((lane >> 3) & 1) * 16;

    // load-to-regs indices: 512 float4 per matrix per stage, 2 per thread
    const int ia0 = tid, ia1 = tid + 256;
    const int ra0 = ia0 >> 2, ka0 = ia0 & 3;
    const int ra1 = ia1 >> 2, ka1 = ia1 & 3;

    float4 va0, va1, vb0, vb1;
    float acc[2][8][4];
    #pragma unroll
    for (int i = 0; i < 2; i++)
        #pragma unroll
        for (int j = 0; j < 8; j++)
            #pragma unroll
            for (int q = 0; q < 4; q++) acc[i][j][q] = 0.0f;

    // prologue: stage 0
    va0 = *(const float4*)(pA + (size_t)ra0 * sA + ka0 * 4);
    va1 = *(const float4*)(pA + (size_t)ra1 * sA + ka1 * 4);
    vb0 = *(const float4*)(pB + (size_t)ra0 * sB + ka0 * 4);
    vb1 = *(const float4*)(pB + (size_t)ra1 * sB + ka1 * 4);
    {
        char* base = smem;
        st_hl(base + RAH, base + RAL, (uint32_t)(ra0 * ROWH + ka0 * 4) * 2, va0);
        st_hl(base + RAH, base + RAL, (uint32_t)(ra1 * ROWH + ka1 * 4) * 2, va1);
        st_hl(base + RBH, base + RBL, (uint32_t)(ra0 * ROWH + ka0 * 4) * 2, vb0);
        st_hl(base + RBH, base + RBL, (uint32_t)(ra1 * ROWH + ka1 * 4) * 2, vb1);
    }
    __syncthreads();

    for (int s = 0; s < nst; s++) {
        const int k0 = (s + 1) * 16;
        if (s + 1 < nst) {
            va0 = *(const float4*)(pA + (size_t)ra0 * sA + k0 + ka0 * 4);
            va1 = *(const float4*)(pA + (size_t)ra1 * sA + k0 + ka1 * 4);
            vb0 = *(const float4*)(pB + (size_t)ra0 * sB + k0 + ka0 * 4);
            vb1 = *(const float4*)(pB + (size_t)ra1 * sB + k0 + ka1 * 4);
        }

        // compute current buffer
        const uint32_t bb = sbase + (uint32_t)(s & 1) * BUFB;
        uint32_t ah[2][4], al[2][4], bh[8][2], bl[8][2];
        #pragma unroll
        for (int mi = 0; mi < 2; mi++) {
            uint32_t ro = (uint32_t)(mo + mi * 16) * 48;
            ldm4(ah[mi], bb + RAH + ro + a_off);
            ldm4(al[mi], bb + RAL + ro + a_off);
        }
        #pragma unroll
        for (int ni = 0; ni < 8; ni++) {
            uint32_t ro = (uint32_t)(no + ni * 8) * 48;
            ldm2(bh[ni], bb + RBH + ro + b_off);
            ldm2(bl[ni], bb + RBL + ro + b_off);
        }
        #pragma unroll
        for (int mi = 0; mi < 2; mi++)
            #pragma unroll
            for (int ni = 0; ni < 8; ni++) {
                mma16816(acc[mi][ni], ah[mi], bh[ni]);
                mma16816(acc[mi][ni], ah[mi], bl[ni]);
                mma16816(acc[mi][ni], al[mi], bh[ni]);
            }

        if (s + 1 < nst) {
            char* base = smem + ((s + 1) & 1) * BUFB;
            st_hl(base + RAH, base + RAL, (uint32_t)(ra0 * ROWH + ka0 * 4) * 2, va0);
            st_hl(base + RAH, base + RAL, (uint32_t)(ra1 * ROWH + ka1 * 4) * 2, va1);
            st_hl(base + RBH, base + RBL, (uint32_t)(ra0 * ROWH + ka0 * 4) * 2, vb0);
            st_hl(base + RBH, base + RBL, (uint32_t)(ra1 * ROWH + ka1 * 4) * 2, vb1);
        }
        __syncthreads();
    }

    // epilogue: fragment layout c0,c1 -> (row, col..col+1), c2,c3 -> (row+8, ..)
    const int er = lane >> 2, ec = (lane & 3) * 2;
    #pragma unroll
    for (int mi = 0; mi < 2; mi++)
        #pragma unroll
        for (int ni = 0; ni < 8; ni++) {
            int r0 = mo + mi * 16 + er;
            int c  = no + ni * 8 + ec;
            *(float2*)(out + (size_t)r0 * so + c)       = make_float2(acc[mi][ni][0], acc[mi][ni][1]);
            *(float2*)(out + (size_t)(r0 + 8) * so + c) = make_float2(acc[mi][ni][2], acc[mi][ni][3]);
        }
}

// ---------------------------------------------------------------------------
__global__ void __launch_bounds__(256) transpose_kernel(const float* __restrict__ x) {
    __shared__ float sm[32][257];
    const int n0 = blockIdx.x * 32, c0 = blockIdx.y * 256, b = blockIdx.z;
    const int t = threadIdx.x;
    const float* Xb = x + (size_t)b * NDIM * CDIM;
    #pragma unroll
    for (int r = 0; r < 32; r++) sm[r][t] = Xb[(size_t)(n0 + r) * CDIM + c0 + t];
    __syncthreads();
    const int n4 = (t & 7) * 4;
    #pragma unroll
    for (int g = 0; g < 8; g++) {
        int cl = g * 32 + (t >> 3);
        float4 v = make_float4(sm[n4][cl], sm[n4 + 1][cl], sm[n4 + 2][cl], sm[n4 + 3][cl]);
        *(float4*)(g_Xt + ((size_t)b * CDIM + c0 + cl) * NDIM + n0 + n4) = v;
    }
}

__global__ void __launch_bounds__(256, 1) gram_mma_kernel() {
    const int i0 = blockIdx.x * 128, j0 = blockIdx.y * 128, b = blockIdx.z;
    const float* base = g_Xt + (size_t)b * CDIM * NDIM;
    mma_pipe(base + (size_t)i0 * NDIM, NDIM,
             base + (size_t)j0 * NDIM, NDIM,
             NDIM / 16,
             g_energy + ((size_t)b * CDIM + i0) * CDIM + j0, CDIM);
}

__global__ void __launch_bounds__(256, 1) out_mma_kernel(const float* __restrict__ x,
                                                         float* __restrict__ y) {
    const int n0 = blockIdx.x * 128, i0 = blockIdx.y * 128, b = blockIdx.z;
    mma_pipe(x + (size_t)b * NDIM * CDIM + (size_t)n0 * CDIM, CDIM,
             g_M + ((size_t)b * CDIM + i0) * CDIM, CDIM,
             CDIM / 16,
             y + ((size_t)b * NDIM + n0) * CDIM + i0, CDIM);
}

__global__ void __launch_bounds__(256) softmax_kernel(const float* __restrict__ gp) {
    const int i = blockIdx.x, b = blockIdx.y;
    const float* e = g_energy + ((size_t)b * CDIM + i) * CDIM;
    __shared__ float sm[256];
    const int t = threadIdx.x;
    float v0 = e[t], v1 = e[t + 256];
    sm[t] = fminf(v0, v1);
    __syncthreads();
    for (int s = 128; s > 0; s >>= 1) { if (t < s) sm[t] = fminf(sm[t], sm[t + s]); __syncthreads(); }
    float mn = sm[0];
    __syncthreads();
    float w0 = __expf(mn - v0), w1 = __expf(mn - v1);
    sm[t] = w0 + w1;
    __syncthreads();
    for (int s = 128; s > 0; s >>= 1) { if (t < s) sm[t] += sm[t + s]; __syncthreads(); }
    float inv = gp[0] / sm[0];
    size_t o = ((size_t)b * CDIM + i) * CDIM;
    g_M[o + t]       = w0 * inv + (t == i ? 1.0f : 0.0f);
    g_M[o + t + 256] = w1 * inv + (t + 256 == i ? 1.0f : 0.0f);
}

extern "C" void kernel_launch(void* const* d_in, const int* in_sizes, int n_in,
                              void* d_out, int out_size) {
    const float* x  = (const float*)d_in[0];
    const float* gm = (const float*)d_in[1];
    float*       y  = (float*)d_out;
    (void)in_sizes; (void)n_in; (void)out_size;

    cudaFuncSetAttribute(gram_mma_kernel, cudaFuncAttributeMaxDynamicSharedMemorySize, SMEM_TOT);
    cudaFuncSetAttribute(out_mma_kernel,  cudaFuncAttributeMaxDynamicSharedMemorySize, SMEM_TOT);

    transpose_kernel<<<dim3(NDIM / 32, CDIM / 256, BATCH), 256>>>(x);
    gram_mma_kernel<<<dim3(4, 4, BATCH), 256, SMEM_TOT>>>();
    softmax_kernel<<<dim3(CDIM, BATCH), 256>>>(gm);
    out_mma_kernel<<<dim3(NDIM / 128, 4, BATCH), 256, SMEM_TOT>>>(x, y);
}